// round 1
// baseline (speedup 1.0000x reference)
#include <cuda_runtime.h>
#include <cuda_bf16.h>
#include <math.h>

// MIL loss: 16384 segments x 1024 frames, top-k (k=128) mean pooling + BCE.
// Plan: one CTA per segment. Exact top-128 sum via 4-pass 8-bit radix select
// on float bit patterns (all values positive => uint order == float order).
// Deterministic: fixed-order tree reductions, no float atomics to gmem.

#define NSEG    16384
#define SEGLEN  1024
#define KSEL    128
#define TPB     256

__device__ float g_seg_loss[NSEG];

__global__ void __launch_bounds__(TPB) mil_seg_kernel(const float* __restrict__ y_pred,
                                                      const float* __restrict__ y) {
    const int seg = blockIdx.x;
    const int tid = threadIdx.x;
    const size_t base = (size_t)seg * SEGLEN;

    // Vectorized coalesced loads: 256 threads x float4 = 1024 elems.
    float4 v = reinterpret_cast<const float4*>(y_pred + base)[tid];
    float4 w = reinterpret_cast<const float4*>(y      + base)[tid];

    unsigned u[4];
    u[0] = __float_as_uint(v.x);
    u[1] = __float_as_uint(v.y);
    u[2] = __float_as_uint(v.z);
    u[3] = __float_as_uint(v.w);
    float ysum = (w.x + w.y) + (w.z + w.w);

    __shared__ unsigned hist[256];
    __shared__ unsigned scan[256];
    __shared__ unsigned sh_prefix;
    __shared__ unsigned sh_needed;

    unsigned prefix = 0u;   // selected high bits of the k-th largest value
    unsigned needed = KSEL; // how many elements still to pick within prefix

    #pragma unroll
    for (int byte = 3; byte >= 0; --byte) {
        const int shift = byte * 8;

        hist[tid] = 0u;
        __syncthreads();

        #pragma unroll
        for (int i = 0; i < 4; ++i) {
            bool active = (byte == 3) || (((u[i] ^ prefix) >> (shift + 8)) == 0u);
            if (active) atomicAdd(&hist[(u[i] >> shift) & 255u], 1u);
        }
        __syncthreads();

        // Inclusive suffix scan: scan[j] = sum_{i >= j} hist[i]  (Hillis-Steele)
        scan[tid] = hist[tid];
        __syncthreads();
        #pragma unroll
        for (int off = 1; off < 256; off <<= 1) {
            unsigned add = (tid + off < 256) ? scan[tid + off] : 0u;
            __syncthreads();
            scan[tid] += add;
            __syncthreads();
        }

        // Find crossing bin b: count(> b) < needed <= count(>= b)
        unsigned cAbove = (tid == 255) ? 0u : scan[tid + 1];
        if (cAbove < needed && scan[tid] >= needed) {
            sh_prefix = prefix | ((unsigned)tid << shift);
            sh_needed = needed - cAbove;
        }
        __syncthreads();
        prefix = sh_prefix;
        needed = sh_needed;
        __syncthreads();
    }

    // prefix == exact bit pattern T of the k-th largest element;
    // needed == number of copies of T inside the top-k (tie handling).
    const unsigned T = prefix;
    float sum_gt = 0.0f;
    #pragma unroll
    for (int i = 0; i < 4; ++i)
        if (u[i] > T) sum_gt += __uint_as_float(u[i]);

    // Deterministic block tree reductions.
    __shared__ float red[TPB];
    red[tid] = sum_gt;
    __syncthreads();
    #pragma unroll
    for (int s = TPB / 2; s > 0; s >>= 1) {
        if (tid < s) red[tid] += red[tid + s];
        __syncthreads();
    }
    float top_sum = red[0];
    __syncthreads();

    red[tid] = ysum;
    __syncthreads();
    #pragma unroll
    for (int s = TPB / 2; s > 0; s >>= 1) {
        if (tid < s) red[tid] += red[tid + s];
        __syncthreads();
    }

    if (tid == 0) {
        float Tf = __uint_as_float(T);
        float p  = (top_sum + (float)needed * Tf) * (1.0f / (float)KSEL);
        float t  = red[0] * (1.0f / (float)SEGLEN);
        float loss = -(t * logf(p) + (1.0f - t) * log1pf(-p));
        g_seg_loss[seg] = loss;
    }
}

__global__ void __launch_bounds__(1024) mil_reduce_kernel(float* __restrict__ out) {
    __shared__ float red[1024];
    float s = 0.0f;
    for (int i = threadIdx.x; i < NSEG; i += 1024)
        s += g_seg_loss[i];
    red[threadIdx.x] = s;
    __syncthreads();
    #pragma unroll
    for (int off = 512; off > 0; off >>= 1) {
        if (threadIdx.x < off) red[threadIdx.x] += red[threadIdx.x + off];
        __syncthreads();
    }
    if (threadIdx.x == 0)
        out[0] = red[0] * (1.0f / (float)NSEG);
}

extern "C" void kernel_launch(void* const* d_in, const int* in_sizes, int n_in,
                              void* d_out, int out_size) {
    const float* y_pred = (const float*)d_in[0];
    const float* y      = (const float*)d_in[1];
    // d_in[2] = segment_key (consecutive, uniform length) -> index math instead.
    mil_seg_kernel<<<NSEG, TPB>>>(y_pred, y);
    mil_reduce_kernel<<<1, 1024>>>((float*)d_out);
}